// round 1
// baseline (speedup 1.0000x reference)
#include <cuda_runtime.h>
#include <math.h>

#define SEQ 8192
#define DIM 512

// Scratch (allocation-free rule: __device__ globals)
__device__ float g_Q[SEQ * DIM];
__device__ float g_K[SEQ * DIM];
__device__ float g_V[SEQ * DIM];

// ---------------------------------------------------------------------------
// NT GEMM: C[M,N] = A[M,K] @ B[N,K]^T  (both row-major, K contiguous)
// 128x128 block, BK=16, 256 threads, 8x8 micro-tile per thread.
// CAUSAL: skip blocks strictly above the diagonal (requires M==N tiles).
// BIAS:   C += bias[col] (used for QKV projections).
// scale applied before bias.
// ---------------------------------------------------------------------------
template<bool CAUSAL, bool BIAS>
__global__ __launch_bounds__(256) void gemm_nt(const float* __restrict__ A,
                                               const float* __restrict__ B,
                                               const float* __restrict__ bias,
                                               float* __restrict__ C,
                                               int M, int N, int K, float scale)
{
    constexpr int BM = 128, BN = 128, BK = 16;
    const int bx = blockIdx.x, by = blockIdx.y;
    if (CAUSAL && bx > by) return;

    __shared__ float As[BK][BM + 4];
    __shared__ float Bs[BK][BN + 4];

    const int tid = threadIdx.x;
    const int tx = tid & 15;   // 0..15 -> N direction
    const int ty = tid >> 4;   // 0..15 -> M direction

    const float* Ab = A + (size_t)by * BM * K;
    const float* Bb = B + (size_t)bx * BN * K;

    float acc[8][8] = {};

    for (int k0 = 0; k0 < K; k0 += BK) {
        #pragma unroll
        for (int p = 0; p < 2; p++) {
            int f = tid + p * 256;     // 0..511 float4 slots (128 rows x 4)
            int r = f >> 2;            // 0..127
            int c = (f & 3) * 4;       // 0,4,8,12
            float4 av = *(const float4*)(Ab + (size_t)r * K + k0 + c);
            float4 bv = *(const float4*)(Bb + (size_t)r * K + k0 + c);
            As[c + 0][r] = av.x; As[c + 1][r] = av.y;
            As[c + 2][r] = av.z; As[c + 3][r] = av.w;
            Bs[c + 0][r] = bv.x; Bs[c + 1][r] = bv.y;
            Bs[c + 2][r] = bv.z; Bs[c + 3][r] = bv.w;
        }
        __syncthreads();

        #pragma unroll
        for (int k = 0; k < BK; k++) {
            float a[8], b[8];
            #pragma unroll
            for (int i = 0; i < 8; i++) a[i] = As[k][ty * 8 + i];
            #pragma unroll
            for (int j = 0; j < 8; j++) b[j] = Bs[k][tx * 8 + j];
            #pragma unroll
            for (int i = 0; i < 8; i++)
                #pragma unroll
                for (int j = 0; j < 8; j++)
                    acc[i][j] = fmaf(a[i], b[j], acc[i][j]);
        }
        __syncthreads();
    }

    #pragma unroll
    for (int i = 0; i < 8; i++) {
        int row = by * BM + ty * 8 + i;
        #pragma unroll
        for (int j = 0; j < 8; j += 4) {
            int col = bx * BN + tx * 8 + j;
            float4 v;
            v.x = acc[i][j + 0] * scale;
            v.y = acc[i][j + 1] * scale;
            v.z = acc[i][j + 2] * scale;
            v.w = acc[i][j + 3] * scale;
            if (BIAS) {
                v.x += bias[col + 0];
                v.y += bias[col + 1];
                v.z += bias[col + 2];
                v.w += bias[col + 3];
            }
            *(float4*)(C + (size_t)row * N + col) = v;
        }
    }
}

// ---------------------------------------------------------------------------
// NN GEMM: C[M,N] = A[M,K] @ B[K,N]  (row-major). Used for attn @ V.
// K loop truncated to the last row of the block (attn upper triangle == 0).
// ---------------------------------------------------------------------------
__global__ __launch_bounds__(256) void gemm_nn(const float* __restrict__ A,
                                               const float* __restrict__ B,
                                               float* __restrict__ C,
                                               int M, int N, int K)
{
    constexpr int BM = 128, BN = 128, BK = 16;
    const int bx = blockIdx.x, by = blockIdx.y;

    __shared__ float As[BK][BM + 4];
    __shared__ float Bs[BK][BN + 4];

    const int tid = threadIdx.x;
    const int tx = tid & 15;
    const int ty = tid >> 4;

    const float* Ab = A + (size_t)by * BM * K;

    float acc[8][8] = {};

    const int kmax = min(K, (by + 1) * BM);   // rows beyond block's last row are zero

    for (int k0 = 0; k0 < kmax; k0 += BK) {
        #pragma unroll
        for (int p = 0; p < 2; p++) {
            int f = tid + p * 256;
            // A tile: 128 rows x 16 k (k contiguous)
            int ar = f >> 2;
            int ac = (f & 3) * 4;
            float4 av = *(const float4*)(Ab + (size_t)ar * K + k0 + ac);
            As[ac + 0][ar] = av.x; As[ac + 1][ar] = av.y;
            As[ac + 2][ar] = av.z; As[ac + 3][ar] = av.w;
            // B tile: 16 k-rows x 128 n (n contiguous)
            int br = f >> 5;           // 0..15
            int bc = (f & 31) * 4;     // 0..124
            float4 bv = *(const float4*)(B + (size_t)(k0 + br) * N + bx * BN + bc);
            *(float4*)&Bs[br][bc] = bv;
        }
        __syncthreads();

        #pragma unroll
        for (int k = 0; k < BK; k++) {
            float a[8], b[8];
            #pragma unroll
            for (int i = 0; i < 8; i++) a[i] = As[k][ty * 8 + i];
            #pragma unroll
            for (int j = 0; j < 8; j++) b[j] = Bs[k][tx * 8 + j];
            #pragma unroll
            for (int i = 0; i < 8; i++)
                #pragma unroll
                for (int j = 0; j < 8; j++)
                    acc[i][j] = fmaf(a[i], b[j], acc[i][j]);
        }
        __syncthreads();
    }

    #pragma unroll
    for (int i = 0; i < 8; i++) {
        int row = by * BM + ty * 8 + i;
        #pragma unroll
        for (int j = 0; j < 8; j += 4) {
            int col = bx * BN + tx * 8 + j;
            float4 v = make_float4(acc[i][j], acc[i][j + 1], acc[i][j + 2], acc[i][j + 3]);
            *(float4*)(C + (size_t)row * N + col) = v;
        }
    }
}

// ---------------------------------------------------------------------------
// In-place causal softmax over attn rows. One block per row.
// Row i: valid cols [0, i]; cols (i, SEQ) are zeroed (covers skipped tiles
// and the poisoned output region above the diagonal).
// ---------------------------------------------------------------------------
__global__ __launch_bounds__(256) void softmax_causal(float* __restrict__ attn)
{
    extern __shared__ float row[];       // SEQ floats (32 KB)
    __shared__ float red[33];

    const int i = blockIdx.x;
    const int n = i + 1;
    const int tid = threadIdx.x;
    float* p = attn + (size_t)i * SEQ;

    // Load + local max
    float m = -1e30f;
    for (int j = tid; j < n; j += 256) {
        float v = p[j];
        row[j] = v;
        m = fmaxf(m, v);
    }
    #pragma unroll
    for (int o = 16; o; o >>= 1) m = fmaxf(m, __shfl_xor_sync(0xffffffffu, m, o));
    if ((tid & 31) == 0) red[tid >> 5] = m;
    __syncthreads();
    if (tid < 32) {
        float v = (tid < 8) ? red[tid] : -1e30f;
        #pragma unroll
        for (int o = 4; o; o >>= 1) v = fmaxf(v, __shfl_xor_sync(0xffffffffu, v, o));
        if (tid == 0) red[32] = v;
    }
    __syncthreads();
    const float rowmax = red[32];
    __syncthreads();

    // exp + local sum
    float s = 0.0f;
    for (int j = tid; j < n; j += 256) {
        float e = __expf(row[j] - rowmax);
        row[j] = e;
        s += e;
    }
    #pragma unroll
    for (int o = 16; o; o >>= 1) s += __shfl_xor_sync(0xffffffffu, s, o);
    if ((tid & 31) == 0) red[tid >> 5] = s;
    __syncthreads();
    if (tid < 32) {
        float v = (tid < 8) ? red[tid] : 0.0f;
        #pragma unroll
        for (int o = 4; o; o >>= 1) v += __shfl_xor_sync(0xffffffffu, v, o);
        if (tid == 0) red[32] = v;
    }
    __syncthreads();
    const float inv = 1.0f / red[32];

    for (int j = tid; j < n; j += 256) p[j] = row[j] * inv;
    for (int j = n + tid; j < SEQ; j += 256) p[j] = 0.0f;
}

// ---------------------------------------------------------------------------
extern "C" void kernel_launch(void* const* d_in, const int* in_sizes, int n_in,
                              void* d_out, int out_size)
{
    const float* x  = (const float*)d_in[0];
    const float* Wq = (const float*)d_in[1];
    const float* bq = (const float*)d_in[2];
    const float* Wk = (const float*)d_in[3];
    const float* bk = (const float*)d_in[4];
    const float* Wv = (const float*)d_in[5];
    const float* bv = (const float*)d_in[6];

    float* out  = (float*)d_out;                    // [SEQ, DIM]
    float* attn = out + (size_t)SEQ * DIM;          // [SEQ, SEQ]

    float *Q, *K, *V;
    cudaGetSymbolAddress((void**)&Q, g_Q);
    cudaGetSymbolAddress((void**)&K, g_K);
    cudaGetSymbolAddress((void**)&V, g_V);

    const float inv_sqrt_d = 0.04419417382415922f;  // 1/sqrt(512)

    // QKV projections: [8192,512] @ [512,512]^T + bias
    dim3 gqkv(DIM / 128, SEQ / 128);
    gemm_nt<false, true><<<gqkv, 256>>>(x, Wq, bq, Q, SEQ, DIM, DIM, 1.0f);
    gemm_nt<false, true><<<gqkv, 256>>>(x, Wk, bk, K, SEQ, DIM, DIM, 1.0f);
    gemm_nt<false, true><<<gqkv, 256>>>(x, Wv, bv, V, SEQ, DIM, DIM, 1.0f);

    // scores = (Q @ K^T) * inv_sqrt_d  -> attn buffer (lower-triangle tiles only)
    dim3 gsc(SEQ / 128, SEQ / 128);
    gemm_nt<true, false><<<gsc, 256>>>(Q, K, nullptr, attn, SEQ, SEQ, DIM, inv_sqrt_d);

    // in-place causal softmax (also zeroes upper triangle)
    softmax_causal<<<SEQ, 256, SEQ * sizeof(float)>>>(attn);

    // output = attn @ V  (K truncated per row-block)
    dim3 gav(DIM / 128, SEQ / 128);
    gemm_nn<<<gav, 256>>>(attn, V, out, SEQ, DIM, SEQ);
}

// round 7
// speedup vs baseline: 2.9502x; 2.9502x over previous
#include <cuda_runtime.h>
#include <cuda_bf16.h>
#include <math.h>
#include <stdint.h>

#define SEQ 8192
#define DIM 512

// ---------------------------------------------------------------------------
// Scratch (allocation-free rule: __device__ globals)
// ---------------------------------------------------------------------------
__device__ __nv_bfloat16 g_xh[SEQ * DIM], g_xl[SEQ * DIM];
__device__ __nv_bfloat16 g_Wqh[DIM * DIM], g_Wql[DIM * DIM];
__device__ __nv_bfloat16 g_Wkh[DIM * DIM], g_Wkl[DIM * DIM];
__device__ __nv_bfloat16 g_Wvh[DIM * DIM], g_Wvl[DIM * DIM];
__device__ __nv_bfloat16 g_Qh[SEQ * DIM], g_Ql[SEQ * DIM];
__device__ __nv_bfloat16 g_Kh[SEQ * DIM], g_Kl[SEQ * DIM];
__device__ float         g_V[SEQ * DIM];
__device__ __nv_bfloat16 g_Vth[DIM * SEQ], g_Vtl[DIM * SEQ];
__device__ __nv_bfloat16 g_Ath[(size_t)SEQ * SEQ], g_Atl[(size_t)SEQ * SEQ];

// ---------------------------------------------------------------------------
// PTX helpers (baseline ISA only — no tcgen05 on this toolchain's sm_103 target)
// ---------------------------------------------------------------------------
__device__ __forceinline__ uint32_t smem_u32(const void* p) {
    uint32_t a;
    asm("{ .reg .u64 t; cvta.to.shared.u64 t, %1; cvt.u32.u64 %0, t; }" : "=r"(a) : "l"(p));
    return a;
}
__device__ __forceinline__ void cp16(uint32_t dst, const void* src) {
    asm volatile("cp.async.cg.shared.global [%0], [%1], 16;" :: "r"(dst), "l"(src) : "memory");
}
__device__ __forceinline__ void cp_commit() { asm volatile("cp.async.commit_group;" ::: "memory"); }
__device__ __forceinline__ void cp_wait1()  { asm volatile("cp.async.wait_group 1;"  ::: "memory"); }

#define SW128(o) ((o) ^ (((o) >> 3) & 0x70))

#define LDSM4(r, a)                                                              \
    asm volatile("ldmatrix.sync.aligned.m8n8.x4.shared.b16 {%0,%1,%2,%3}, [%4];" \
        : "=r"((r)[0]), "=r"((r)[1]), "=r"((r)[2]), "=r"((r)[3]) : "r"(a))

#define MMA16816(c, a, b0, b1)                                                   \
    asm volatile("mma.sync.aligned.m16n8k16.row.col.f32.bf16.bf16.f32 "          \
        "{%0,%1,%2,%3}, {%4,%5,%6,%7}, {%8,%9}, {%0,%1,%2,%3};"                  \
        : "+f"((c)[0]), "+f"((c)[1]), "+f"((c)[2]), "+f"((c)[3])                 \
        : "r"((a)[0]), "r"((a)[1]), "r"((a)[2]), "r"((a)[3]), "r"(b0), "r"(b1))

// ---------------------------------------------------------------------------
// HMMA NT GEMM: C[M,N] = (Ah+Al)[M,Kd] @ (Bh+Bl)[N,Kd]^T  (3-term split)
// MODE: 0 = QK  (bias, split-bf16 output Ch/Cl)
//       1 = VF  (bias, fp32 output Cf)
//       2 = SC  (causal tile skip, scale, fp32 output)
//       3 = AV  (K truncated to (by+1)*128, fp32 output)
// BM=BN=128, BK=64 (128B rows, SW128), 256 threads, 8 warps x (64x32 tile).
// Double-buffered cp.async: 2 stages x 4 tiles x 16KB = 128KB smem.
// ---------------------------------------------------------------------------
#define TILE_B 16384
#define SMEM_TILES (8 * TILE_B)
#define GEMM_SMEM (SMEM_TILES + 1024)

template<int MODE>
__global__ __launch_bounds__(256) void mma_gemm(
    const __nv_bfloat16* __restrict__ Ah, const __nv_bfloat16* __restrict__ Al,
    const __nv_bfloat16* __restrict__ Bh, const __nv_bfloat16* __restrict__ Bl,
    const float* __restrict__ bias,
    float* __restrict__ Cf, __nv_bfloat16* __restrict__ Ch, __nv_bfloat16* __restrict__ Cl,
    int Nld, int Kd, float scale)
{
    const int bx = blockIdx.x, by = blockIdx.y;
    if (MODE == 2 && bx > by) return;

    extern __shared__ char dsm[];
    uint32_t sb = smem_u32(dsm);
    sb = (sb + 1023) & ~1023u;

    const int tid  = threadIdx.x;
    const int wid  = tid >> 5;
    const int lane = tid & 31;
    const int m0   = (wid >> 2) * 64;   // warp M origin (0 or 64)
    const int n0   = (wid & 3) * 32;    // warp N origin (0,32,64,96)

    const int kmax    = (MODE == 3) ? (by + 1) * 128 : Kd;
    const int nchunks = kmax >> 6;      // >= 2 always

    const __nv_bfloat16* P[4];
    P[0] = Ah + (size_t)by * 128 * Kd;
    P[1] = Al + (size_t)by * 128 * Kd;
    P[2] = Bh + (size_t)bx * 128 * Kd;
    P[3] = Bl + (size_t)bx * 128 * Kd;

    // loader: 4 tiles x 128 rows x 8 segs(16B) = 4096 cp / 256 thr
    auto load_chunk = [&](int s, int chunk) {
        const uint32_t stage_base = sb + s * 4 * TILE_B;
        #pragma unroll
        for (int i = 0; i < 4; i++) {
            int idx = tid + i * 256;
            int row = idx >> 3;
            int seg = idx & 7;
            uint32_t so = SW128((uint32_t)(row * 128 + seg * 16));
            #pragma unroll
            for (int t = 0; t < 4; t++) {
                const __nv_bfloat16* src = P[t] + (size_t)row * Kd + chunk * 64 + seg * 8;
                cp16(stage_base + t * TILE_B + so, src);
            }
        }
        cp_commit();
    };

    float c[4][4][4] = {};

    // ldmatrix lane addressing (SW128: XOR (row&7)<<4 into the 16B-seg bits)
    const int la = lane & 15;                       // A: rows 0..15
    const int sa = lane >> 4;                       // A: k-seg select
    const int lb = (lane & 7) | ((lane >> 4) << 3); // B: rows 0..7 / 8..15
    const int sbg = (lane >> 3) & 1;                // B: k-seg select
    const uint32_t xa = (uint32_t)(lane & 7) << 4;
    const uint32_t aRowOff = (uint32_t)(m0 + la) * 128;
    const uint32_t bRowOff = (uint32_t)(n0 + lb) * 128;

    auto compute = [&](int s) {
        const uint32_t base = sb + s * 4 * TILE_B;
        const uint32_t bAh = base, bAl = base + TILE_B;
        const uint32_t bBh = base + 2 * TILE_B, bBl = base + 3 * TILE_B;
        #pragma unroll
        for (int ks = 0; ks < 4; ks++) {
            const uint32_t ka = ((uint32_t)(ks * 32 + sa * 16)) ^ xa;
            const uint32_t kb = ((uint32_t)(ks * 32 + sbg * 16)) ^ xa;
            uint32_t ah[4][4], al[4][4], bh[4][2], bl[4][2];
            #pragma unroll
            for (int mt = 0; mt < 4; mt++) LDSM4(ah[mt], bAh + aRowOff + mt * 2048 + ka);
            #pragma unroll
            for (int mt = 0; mt < 4; mt++) LDSM4(al[mt], bAl + aRowOff + mt * 2048 + ka);
            #pragma unroll
            for (int np = 0; np < 2; np++) {
                uint32_t t4[4];
                LDSM4(t4, bBh + bRowOff + np * 2048 + kb);
                bh[2 * np][0] = t4[0]; bh[2 * np][1] = t4[1];
                bh[2 * np + 1][0] = t4[2]; bh[2 * np + 1][1] = t4[3];
                LDSM4(t4, bBl + bRowOff + np * 2048 + kb);
                bl[2 * np][0] = t4[0]; bl[2 * np][1] = t4[1];
                bl[2 * np + 1][0] = t4[2]; bl[2 * np + 1][1] = t4[3];
            }
            #pragma unroll
            for (int mt = 0; mt < 4; mt++)
                #pragma unroll
                for (int nt = 0; nt < 4; nt++) {
                    MMA16816(c[mt][nt], ah[mt], bh[nt][0], bh[nt][1]);
                    MMA16816(c[mt][nt], ah[mt], bl[nt][0], bl[nt][1]);
                    MMA16816(c[mt][nt], al[mt], bh[nt][0], bh[nt][1]);
                }
        }
    };

    load_chunk(0, 0);
    load_chunk(1, 1);

    for (int i = 0; i < nchunks; i++) {
        const int s = i & 1;
        cp_wait1();
        __syncthreads();
        compute(s);
        __syncthreads();
        if (i + 2 < nchunks) load_chunk(s, i + 2);
        else cp_commit();
    }

    // Epilogue: C frag -> global. thread: rows g, g+8; col pair 2t.
    const int g = lane >> 2, t = lane & 3;
    #pragma unroll
    for (int mt = 0; mt < 4; mt++) {
        #pragma unroll
        for (int nt = 0; nt < 4; nt++) {
            const int col = bx * 128 + n0 + nt * 8 + t * 2;
            #pragma unroll
            for (int h = 0; h < 2; h++) {
                const int row = by * 128 + m0 + mt * 16 + g + h * 8;
                float v0 = c[mt][nt][2 * h + 0];
                float v1 = c[mt][nt][2 * h + 1];
                if (MODE == 0 || MODE == 1) { v0 += bias[col]; v1 += bias[col + 1]; }
                if (MODE == 2) { v0 *= scale; v1 *= scale; }
                const size_t o = (size_t)row * Nld + col;
                if (MODE == 0) {
                    __nv_bfloat16 h0 = __float2bfloat16(v0);
                    __nv_bfloat16 h1 = __float2bfloat16(v1);
                    __nv_bfloat16 l0 = __float2bfloat16(v0 - __bfloat162float(h0));
                    __nv_bfloat16 l1 = __float2bfloat16(v1 - __bfloat162float(h1));
                    *(__nv_bfloat162*)(Ch + o) = __nv_bfloat162(h0, h1);
                    *(__nv_bfloat162*)(Cl + o) = __nv_bfloat162(l0, l1);
                } else {
                    *(float2*)(Cf + o) = make_float2(v0, v1);
                }
            }
        }
    }
}

// ---------------------------------------------------------------------------
// fp32 -> bf16 hi/lo split (elementwise)
// ---------------------------------------------------------------------------
__global__ __launch_bounds__(256) void split_f32(const float* __restrict__ in,
                                                 __nv_bfloat16* __restrict__ hi,
                                                 __nv_bfloat16* __restrict__ lo, int n4)
{
    int i = blockIdx.x * 256 + threadIdx.x;
    if (i >= n4) return;
    float4 v = ((const float4*)in)[i];
    __nv_bfloat16 h[4], l[4];
    float f[4] = {v.x, v.y, v.z, v.w};
    #pragma unroll
    for (int k = 0; k < 4; k++) {
        h[k] = __float2bfloat16(f[k]);
        l[k] = __float2bfloat16(f[k] - __bfloat162float(h[k]));
    }
    ((__nv_bfloat162*)hi)[i * 2]     = __nv_bfloat162(h[0], h[1]);
    ((__nv_bfloat162*)hi)[i * 2 + 1] = __nv_bfloat162(h[2], h[3]);
    ((__nv_bfloat162*)lo)[i * 2]     = __nv_bfloat162(l[0], l[1]);
    ((__nv_bfloat162*)lo)[i * 2 + 1] = __nv_bfloat162(l[2], l[3]);
}

// ---------------------------------------------------------------------------
// V [SEQ, DIM] -> Vt hi/lo [DIM, SEQ] (transpose + split)
// ---------------------------------------------------------------------------
__global__ __launch_bounds__(256) void transpose_split(const float* __restrict__ V,
                                                       __nv_bfloat16* __restrict__ Vth,
                                                       __nv_bfloat16* __restrict__ Vtl)
{
    __shared__ float t[32][33];
    const int x0 = blockIdx.x * 32;
    const int y0 = blockIdx.y * 32;
    const int tx = threadIdx.x & 31, ty = threadIdx.x >> 5;
    #pragma unroll
    for (int i = 0; i < 32; i += 8)
        t[ty + i][tx] = V[(size_t)(y0 + ty + i) * DIM + x0 + tx];
    __syncthreads();
    #pragma unroll
    for (int i = 0; i < 32; i += 8) {
        float v = t[tx][ty + i];
        __nv_bfloat16 h = __float2bfloat16(v);
        __nv_bfloat16 l = __float2bfloat16(v - __bfloat162float(h));
        size_t o = (size_t)(x0 + ty + i) * SEQ + y0 + tx;
        Vth[o] = h;
        Vtl[o] = l;
    }
}

// ---------------------------------------------------------------------------
// In-place causal softmax; also emits attn hi/lo bf16 for the AV GEMM.
// ---------------------------------------------------------------------------
__global__ __launch_bounds__(256) void softmax_causal(float* __restrict__ attn,
                                                      __nv_bfloat16* __restrict__ ah,
                                                      __nv_bfloat16* __restrict__ al)
{
    extern __shared__ float row[];
    __shared__ float red[33];

    const int i = blockIdx.x;
    const int n = i + 1;
    const int tid = threadIdx.x;
    float* p = attn + (size_t)i * SEQ;
    __nv_bfloat16* ph = ah + (size_t)i * SEQ;
    __nv_bfloat16* pl = al + (size_t)i * SEQ;

    float m = -1e30f;
    for (int j = tid; j < n; j += 256) {
        float v = p[j];
        row[j] = v;
        m = fmaxf(m, v);
    }
    #pragma unroll
    for (int o = 16; o; o >>= 1) m = fmaxf(m, __shfl_xor_sync(0xffffffffu, m, o));
    if ((tid & 31) == 0) red[tid >> 5] = m;
    __syncthreads();
    if (tid < 32) {
        float v = (tid < 8) ? red[tid] : -1e30f;
        #pragma unroll
        for (int o = 4; o; o >>= 1) v = fmaxf(v, __shfl_xor_sync(0xffffffffu, v, o));
        if (tid == 0) red[32] = v;
    }
    __syncthreads();
    const float rowmax = red[32];
    __syncthreads();

    float s = 0.0f;
    for (int j = tid; j < n; j += 256) {
        float e = __expf(row[j] - rowmax);
        row[j] = e;
        s += e;
    }
    #pragma unroll
    for (int o = 16; o; o >>= 1) s += __shfl_xor_sync(0xffffffffu, s, o);
    if ((tid & 31) == 0) red[tid >> 5] = s;
    __syncthreads();
    if (tid < 32) {
        float v = (tid < 8) ? red[tid] : 0.0f;
        #pragma unroll
        for (int o = 4; o; o >>= 1) v += __shfl_xor_sync(0xffffffffu, v, o);
        if (tid == 0) red[32] = v;
    }
    __syncthreads();
    const float inv = 1.0f / red[32];

    for (int j = tid; j < n; j += 256) {
        float v = row[j] * inv;
        p[j] = v;
        __nv_bfloat16 h = __float2bfloat16(v);
        ph[j] = h;
        pl[j] = __float2bfloat16(v - __bfloat162float(h));
    }
    const __nv_bfloat16 z = __float2bfloat16(0.0f);
    for (int j = n + tid; j < SEQ; j += 256) {
        p[j] = 0.0f;
        ph[j] = z;
        pl[j] = z;
    }
}

// ---------------------------------------------------------------------------
extern "C" void kernel_launch(void* const* d_in, const int* in_sizes, int n_in,
                              void* d_out, int out_size)
{
    const float* x  = (const float*)d_in[0];
    const float* Wq = (const float*)d_in[1];
    const float* bq = (const float*)d_in[2];
    const float* Wk = (const float*)d_in[3];
    const float* bk = (const float*)d_in[4];
    const float* Wv = (const float*)d_in[5];
    const float* bv = (const float*)d_in[6];

    float* out  = (float*)d_out;                 // [SEQ, DIM]
    float* attn = out + (size_t)SEQ * DIM;       // [SEQ, SEQ]

    __nv_bfloat16 *xh, *xl, *Wqh, *Wql, *Wkh, *Wkl, *Wvh, *Wvl;
    __nv_bfloat16 *Qh, *Ql, *Kh, *Kl, *Vth, *Vtl, *Ath, *Atl;
    float* Vf;
    cudaGetSymbolAddress((void**)&xh, g_xh);   cudaGetSymbolAddress((void**)&xl, g_xl);
    cudaGetSymbolAddress((void**)&Wqh, g_Wqh); cudaGetSymbolAddress((void**)&Wql, g_Wql);
    cudaGetSymbolAddress((void**)&Wkh, g_Wkh); cudaGetSymbolAddress((void**)&Wkl, g_Wkl);
    cudaGetSymbolAddress((void**)&Wvh, g_Wvh); cudaGetSymbolAddress((void**)&Wvl, g_Wvl);
    cudaGetSymbolAddress((void**)&Qh, g_Qh);   cudaGetSymbolAddress((void**)&Ql, g_Ql);
    cudaGetSymbolAddress((void**)&Kh, g_Kh);   cudaGetSymbolAddress((void**)&Kl, g_Kl);
    cudaGetSymbolAddress((void**)&Vth, g_Vth); cudaGetSymbolAddress((void**)&Vtl, g_Vtl);
    cudaGetSymbolAddress((void**)&Ath, g_Ath); cudaGetSymbolAddress((void**)&Atl, g_Atl);
    cudaGetSymbolAddress((void**)&Vf, g_V);

    cudaFuncSetAttribute(mma_gemm<0>, cudaFuncAttributeMaxDynamicSharedMemorySize, GEMM_SMEM);
    cudaFuncSetAttribute(mma_gemm<1>, cudaFuncAttributeMaxDynamicSharedMemorySize, GEMM_SMEM);
    cudaFuncSetAttribute(mma_gemm<2>, cudaFuncAttributeMaxDynamicSharedMemorySize, GEMM_SMEM);
    cudaFuncSetAttribute(mma_gemm<3>, cudaFuncAttributeMaxDynamicSharedMemorySize, GEMM_SMEM);

    const float inv_sqrt_d = 0.04419417382415922f;  // 1/sqrt(512)

    // 1) split inputs to bf16 hi/lo
    split_f32<<<(SEQ * DIM / 4 + 255) / 256, 256>>>(x, xh, xl, SEQ * DIM / 4);
    split_f32<<<(DIM * DIM / 4 + 255) / 256, 256>>>(Wq, Wqh, Wql, DIM * DIM / 4);
    split_f32<<<(DIM * DIM / 4 + 255) / 256, 256>>>(Wk, Wkh, Wkl, DIM * DIM / 4);
    split_f32<<<(DIM * DIM / 4 + 255) / 256, 256>>>(Wv, Wvh, Wvl, DIM * DIM / 4);

    // 2) QKV projections (tensor cores via mma.sync)
    dim3 gqkv(DIM / 128, SEQ / 128);
    mma_gemm<0><<<gqkv, 256, GEMM_SMEM>>>(xh, xl, Wqh, Wql, bq, nullptr, Qh, Ql, DIM, DIM, 1.0f);
    mma_gemm<0><<<gqkv, 256, GEMM_SMEM>>>(xh, xl, Wkh, Wkl, bk, nullptr, Kh, Kl, DIM, DIM, 1.0f);
    mma_gemm<1><<<gqkv, 256, GEMM_SMEM>>>(xh, xl, Wvh, Wvl, bv, Vf, nullptr, nullptr, DIM, DIM, 1.0f);

    // 3) V -> Vt hi/lo
    transpose_split<<<dim3(DIM / 32, SEQ / 32), 256>>>(Vf, Vth, Vtl);

    // 4) scores = (Q @ K^T) * inv_sqrt_d (lower-triangle tiles)
    dim3 gsc(SEQ / 128, SEQ / 128);
    mma_gemm<2><<<gsc, 256, GEMM_SMEM>>>(Qh, Ql, Kh, Kl, nullptr, attn, nullptr, nullptr, SEQ, DIM, inv_sqrt_d);

    // 5) causal softmax (fp32 out + bf16 hi/lo for AV)
    softmax_causal<<<SEQ, 256, SEQ * sizeof(float)>>>(attn, Ath, Atl);

    // 6) out = attn @ V  (B = Vt, K truncated per row-block)
    dim3 gav(DIM / 128, SEQ / 128);
    mma_gemm<3><<<gav, 256, GEMM_SMEM>>>(Ath, Atl, Vth, Vtl, nullptr, out, nullptr, nullptr, DIM, SEQ, 1.0f);
}

// round 9
// speedup vs baseline: 3.0049x; 1.0185x over previous
#include <cuda_runtime.h>
#include <cuda_bf16.h>
#include <math.h>
#include <stdint.h>

#define SEQ 8192
#define DIM 512

// ---------------------------------------------------------------------------
// Scratch (allocation-free rule: __device__ globals)
// ---------------------------------------------------------------------------
__device__ __nv_bfloat16 g_xh[SEQ * DIM], g_xl[SEQ * DIM];
__device__ __nv_bfloat16 g_Wqh[DIM * DIM], g_Wql[DIM * DIM];
__device__ __nv_bfloat16 g_Wkh[DIM * DIM], g_Wkl[DIM * DIM];
__device__ __nv_bfloat16 g_Wvh[DIM * DIM], g_Wvl[DIM * DIM];
__device__ __nv_bfloat16 g_Qh[SEQ * DIM], g_Ql[SEQ * DIM];
__device__ __nv_bfloat16 g_Kh[SEQ * DIM], g_Kl[SEQ * DIM];
__device__ float         g_V[SEQ * DIM];
__device__ __nv_bfloat16 g_Vth[DIM * SEQ], g_Vtl[DIM * SEQ];
__device__ __nv_bfloat16 g_Ath[(size_t)SEQ * SEQ], g_Atl[(size_t)SEQ * SEQ];

// ---------------------------------------------------------------------------
// PTX helpers (baseline ISA only — tcgen05 unavailable on this toolchain)
// ---------------------------------------------------------------------------
__device__ __forceinline__ uint32_t smem_u32(const void* p) {
    uint32_t a;
    asm("{ .reg .u64 t; cvta.to.shared.u64 t, %1; cvt.u32.u64 %0, t; }" : "=r"(a) : "l"(p));
    return a;
}
__device__ __forceinline__ void cp16(uint32_t dst, const void* src) {
    asm volatile("cp.async.cg.shared.global [%0], [%1], 16;" :: "r"(dst), "l"(src) : "memory");
}
__device__ __forceinline__ void cp_commit() { asm volatile("cp.async.commit_group;" ::: "memory"); }
__device__ __forceinline__ void cp_wait1()  { asm volatile("cp.async.wait_group 1;"  ::: "memory"); }

#define SW128(o) ((o) ^ (((o) >> 3) & 0x70))

#define LDSM4(r, a)                                                              \
    asm volatile("ldmatrix.sync.aligned.m8n8.x4.shared.b16 {%0,%1,%2,%3}, [%4];" \
        : "=r"((r)[0]), "=r"((r)[1]), "=r"((r)[2]), "=r"((r)[3]) : "r"(a))

#define MMA16816(c, a, b0, b1)                                                   \
    asm volatile("mma.sync.aligned.m16n8k16.row.col.f32.bf16.bf16.f32 "          \
        "{%0,%1,%2,%3}, {%4,%5,%6,%7}, {%8,%9}, {%0,%1,%2,%3};"                  \
        : "+f"((c)[0]), "+f"((c)[1]), "+f"((c)[2]), "+f"((c)[3])                 \
        : "r"((a)[0]), "r"((a)[1]), "r"((a)[2]), "r"((a)[3]), "r"(b0), "r"(b1))

// ---------------------------------------------------------------------------
// HMMA NT GEMM: C[M,N] = (Ah+Al)[M,Kd] @ (Bh+Bl)[N,Kd]^T  (3-term split)
// MODE: 0 = QK  (bias, split-bf16 output Ch/Cl)
//       1 = VF  (bias, fp32 output Cf)
//       2 = SC  (causal tile skip, scale, fp32 output)
//       3 = AV  (K truncated to (by+1)*128, fp32 output)
// BM=BN=128, BK=64 (128B rows, SW128). 512 threads, 16 warps x (32x32 tile).
// Double-buffered cp.async: 2 stages x 4 tiles x 16KB = 128KB smem.
// ---------------------------------------------------------------------------
#define TILE_B 16384
#define SMEM_TILES (8 * TILE_B)
#define GEMM_SMEM (SMEM_TILES + 1024)

template<int MODE>
__global__ __launch_bounds__(512) void mma_gemm(
    const __nv_bfloat16* __restrict__ Ah, const __nv_bfloat16* __restrict__ Al,
    const __nv_bfloat16* __restrict__ Bh, const __nv_bfloat16* __restrict__ Bl,
    const float* __restrict__ bias,
    float* __restrict__ Cf, __nv_bfloat16* __restrict__ Ch, __nv_bfloat16* __restrict__ Cl,
    int Nld, int Kd, float scale)
{
    const int bx = blockIdx.x, by = blockIdx.y;
    if (MODE == 2 && bx > by) return;

    extern __shared__ char dsm[];
    uint32_t sb = smem_u32(dsm);
    sb = (sb + 1023) & ~1023u;

    const int tid  = threadIdx.x;
    const int wid  = tid >> 5;
    const int lane = tid & 31;
    const int m0   = (wid >> 2) * 32;   // warp M origin (0,32,64,96)
    const int n0   = (wid & 3) * 32;    // warp N origin (0,32,64,96)

    const int kmax    = (MODE == 3) ? (by + 1) * 128 : Kd;
    const int nchunks = kmax >> 6;      // >= 2 always

    const __nv_bfloat16* P[4];
    P[0] = Ah + (size_t)by * 128 * Kd;
    P[1] = Al + (size_t)by * 128 * Kd;
    P[2] = Bh + (size_t)bx * 128 * Kd;
    P[3] = Bl + (size_t)bx * 128 * Kd;

    // loader: 4 tiles x 128 rows x 8 segs(16B) = 4096 cp / 512 thr
    auto load_chunk = [&](int s, int chunk) {
        const uint32_t stage_base = sb + s * 4 * TILE_B;
        #pragma unroll
        for (int i = 0; i < 2; i++) {
            int idx = tid + i * 512;       // 0..1023
            int row = idx >> 3;
            int seg = idx & 7;
            uint32_t so = SW128((uint32_t)(row * 128 + seg * 16));
            #pragma unroll
            for (int t = 0; t < 4; t++) {
                const __nv_bfloat16* src = P[t] + (size_t)row * Kd + chunk * 64 + seg * 8;
                cp16(stage_base + t * TILE_B + so, src);
            }
        }
        cp_commit();
    };

    float c[2][4][4] = {};

    // ldmatrix lane addressing (SW128: XOR (row&7)<<4 into the 16B-seg bits)
    const int la = lane & 15;                       // A: rows 0..15
    const int sa = lane >> 4;                       // A: k-seg select
    const int lb = (lane & 7) | ((lane >> 4) << 3); // B: rows 0..7 / 8..15
    const int sbg = (lane >> 3) & 1;                // B: k-seg select
    const uint32_t xa = (uint32_t)(lane & 7) << 4;
    const uint32_t aRowOff = (uint32_t)(m0 + la) * 128;
    const uint32_t bRowOff = (uint32_t)(n0 + lb) * 128;

    auto compute = [&](int s) {
        const uint32_t base = sb + s * 4 * TILE_B;
        const uint32_t bAh = base, bAl = base + TILE_B;
        const uint32_t bBh = base + 2 * TILE_B, bBl = base + 3 * TILE_B;
        #pragma unroll
        for (int ks = 0; ks < 4; ks++) {
            const uint32_t ka = ((uint32_t)(ks * 32 + sa * 16)) ^ xa;
            const uint32_t kb = ((uint32_t)(ks * 32 + sbg * 16)) ^ xa;
            uint32_t ah[2][4], al[2][4], bh[4][2], bl[4][2];
            #pragma unroll
            for (int mt = 0; mt < 2; mt++) LDSM4(ah[mt], bAh + aRowOff + mt * 2048 + ka);
            #pragma unroll
            for (int mt = 0; mt < 2; mt++) LDSM4(al[mt], bAl + aRowOff + mt * 2048 + ka);
            #pragma unroll
            for (int np = 0; np < 2; np++) {
                uint32_t t4[4];
                LDSM4(t4, bBh + bRowOff + np * 2048 + kb);
                bh[2 * np][0] = t4[0]; bh[2 * np][1] = t4[1];
                bh[2 * np + 1][0] = t4[2]; bh[2 * np + 1][1] = t4[3];
                LDSM4(t4, bBl + bRowOff + np * 2048 + kb);
                bl[2 * np][0] = t4[0]; bl[2 * np][1] = t4[1];
                bl[2 * np + 1][0] = t4[2]; bl[2 * np + 1][1] = t4[3];
            }
            #pragma unroll
            for (int mt = 0; mt < 2; mt++)
                #pragma unroll
                for (int nt = 0; nt < 4; nt++) {
                    MMA16816(c[mt][nt], ah[mt], bh[nt][0], bh[nt][1]);
                    MMA16816(c[mt][nt], ah[mt], bl[nt][0], bl[nt][1]);
                    MMA16816(c[mt][nt], al[mt], bh[nt][0], bh[nt][1]);
                }
        }
    };

    load_chunk(0, 0);
    load_chunk(1, 1);

    for (int i = 0; i < nchunks; i++) {
        const int s = i & 1;
        cp_wait1();
        __syncthreads();
        compute(s);
        __syncthreads();
        if (i + 2 < nchunks) load_chunk(s, i + 2);
        else cp_commit();
    }

    // Epilogue: C frag -> global. thread: rows g, g+8; col pair 2t.
    const int g = lane >> 2, t = lane & 3;
    #pragma unroll
    for (int mt = 0; mt < 2; mt++) {
        #pragma unroll
        for (int nt = 0; nt < 4; nt++) {
            const int col = bx * 128 + n0 + nt * 8 + t * 2;
            #pragma unroll
            for (int h = 0; h < 2; h++) {
                const int row = by * 128 + m0 + mt * 16 + g + h * 8;
                float v0 = c[mt][nt][2 * h + 0];
                float v1 = c[mt][nt][2 * h + 1];
                if (MODE == 0 || MODE == 1) { v0 += bias[col]; v1 += bias[col + 1]; }
                if (MODE == 2) { v0 *= scale; v1 *= scale; }
                const size_t o = (size_t)row * Nld + col;
                if (MODE == 0) {
                    __nv_bfloat16 h0 = __float2bfloat16(v0);
                    __nv_bfloat16 h1 = __float2bfloat16(v1);
                    __nv_bfloat16 l0 = __float2bfloat16(v0 - __bfloat162float(h0));
                    __nv_bfloat16 l1 = __float2bfloat16(v1 - __bfloat162float(h1));
                    *(__nv_bfloat162*)(Ch + o) = __nv_bfloat162(h0, h1);
                    *(__nv_bfloat162*)(Cl + o) = __nv_bfloat162(l0, l1);
                } else {
                    *(float2*)(Cf + o) = make_float2(v0, v1);
                }
            }
        }
    }
}

// ---------------------------------------------------------------------------
// fp32 -> bf16 hi/lo split (elementwise)
// ---------------------------------------------------------------------------
__global__ __launch_bounds__(256) void split_f32(const float* __restrict__ in,
                                                 __nv_bfloat16* __restrict__ hi,
                                                 __nv_bfloat16* __restrict__ lo, int n4)
{
    int i = blockIdx.x * 256 + threadIdx.x;
    if (i >= n4) return;
    float4 v = ((const float4*)in)[i];
    __nv_bfloat16 h[4], l[4];
    float f[4] = {v.x, v.y, v.z, v.w};
    #pragma unroll
    for (int k = 0; k < 4; k++) {
        h[k] = __float2bfloat16(f[k]);
        l[k] = __float2bfloat16(f[k] - __bfloat162float(h[k]));
    }
    ((__nv_bfloat162*)hi)[i * 2]     = __nv_bfloat162(h[0], h[1]);
    ((__nv_bfloat162*)hi)[i * 2 + 1] = __nv_bfloat162(h[2], h[3]);
    ((__nv_bfloat162*)lo)[i * 2]     = __nv_bfloat162(l[0], l[1]);
    ((__nv_bfloat162*)lo)[i * 2 + 1] = __nv_bfloat162(l[2], l[3]);
}

// ---------------------------------------------------------------------------
// V [SEQ, DIM] -> Vt hi/lo [DIM, SEQ] (transpose + split)
// ---------------------------------------------------------------------------
__global__ __launch_bounds__(256) void transpose_split(const float* __restrict__ V,
                                                       __nv_bfloat16* __restrict__ Vth,
                                                       __nv_bfloat16* __restrict__ Vtl)
{
    __shared__ float t[32][33];
    const int x0 = blockIdx.x * 32;
    const int y0 = blockIdx.y * 32;
    const int tx = threadIdx.x & 31, ty = threadIdx.x >> 5;
    #pragma unroll
    for (int i = 0; i < 32; i += 8)
        t[ty + i][tx] = V[(size_t)(y0 + ty + i) * DIM + x0 + tx];
    __syncthreads();
    #pragma unroll
    for (int i = 0; i < 32; i += 8) {
        float v = t[tx][ty + i];
        __nv_bfloat16 h = __float2bfloat16(v);
        __nv_bfloat16 l = __float2bfloat16(v - __bfloat162float(h));
        size_t o = (size_t)(x0 + ty + i) * SEQ + y0 + tx;
        Vth[o] = h;
        Vtl[o] = l;
    }
}

// ---------------------------------------------------------------------------
// In-place causal softmax; emits attn hi/lo bf16 for the AV GEMM.
// bf16 zero-fill only to the next 128 boundary (AV truncates K there);
// fp32 upper triangle zeroed fully (required output).
// ---------------------------------------------------------------------------
__global__ __launch_bounds__(256) void softmax_causal(float* __restrict__ attn,
                                                      __nv_bfloat16* __restrict__ ah,
                                                      __nv_bfloat16* __restrict__ al)
{
    extern __shared__ float row[];
    __shared__ float red[33];

    const int i = blockIdx.x;
    const int n = i + 1;
    const int tid = threadIdx.x;
    float* p = attn + (size_t)i * SEQ;
    __nv_bfloat16* ph = ah + (size_t)i * SEQ;
    __nv_bfloat16* pl = al + (size_t)i * SEQ;

    float m = -1e30f;
    for (int j = tid; j < n; j += 256) {
        float v = p[j];
        row[j] = v;
        m = fmaxf(m, v);
    }
    #pragma unroll
    for (int o = 16; o; o >>= 1) m = fmaxf(m, __shfl_xor_sync(0xffffffffu, m, o));
    if ((tid & 31) == 0) red[tid >> 5] = m;
    __syncthreads();
    if (tid < 32) {
        float v = (tid < 8) ? red[tid] : -1e30f;
        #pragma unroll
        for (int o = 4; o; o >>= 1) v = fmaxf(v, __shfl_xor_sync(0xffffffffu, v, o));
        if (tid == 0) red[32] = v;
    }
    __syncthreads();
    const float rowmax = red[32];
    __syncthreads();

    float s = 0.0f;
    for (int j = tid; j < n; j += 256) {
        float e = __expf(row[j] - rowmax);
        row[j] = e;
        s += e;
    }
    #pragma unroll
    for (int o = 16; o; o >>= 1) s += __shfl_xor_sync(0xffffffffu, s, o);
    if ((tid & 31) == 0) red[tid >> 5] = s;
    __syncthreads();
    if (tid < 32) {
        float v = (tid < 8) ? red[tid] : 0.0f;
        #pragma unroll
        for (int o = 4; o; o >>= 1) v += __shfl_xor_sync(0xffffffffu, v, o);
        if (tid == 0) red[32] = v;
    }
    __syncthreads();
    const float inv = 1.0f / red[32];

    for (int j = tid; j < n; j += 256) {
        float v = row[j] * inv;
        p[j] = v;
        __nv_bfloat16 h = __float2bfloat16(v);
        ph[j] = h;
        pl[j] = __float2bfloat16(v - __bfloat162float(h));
    }
    const int nend = (n + 127) & ~127;            // AV never reads past this
    const __nv_bfloat16 z = __float2bfloat16(0.0f);
    for (int j = n + tid; j < nend; j += 256) {
        ph[j] = z;
        pl[j] = z;
    }
    for (int j = n + tid; j < SEQ; j += 256) p[j] = 0.0f;
}

// ---------------------------------------------------------------------------
extern "C" void kernel_launch(void* const* d_in, const int* in_sizes, int n_in,
                              void* d_out, int out_size)
{
    const float* x  = (const float*)d_in[0];
    const float* Wq = (const float*)d_in[1];
    const float* bq = (const float*)d_in[2];
    const float* Wk = (const float*)d_in[3];
    const float* bk = (const float*)d_in[4];
    const float* Wv = (const float*)d_in[5];
    const float* bv = (const float*)d_in[6];

    float* out  = (float*)d_out;                 // [SEQ, DIM]
    float* attn = out + (size_t)SEQ * DIM;       // [SEQ, SEQ]

    __nv_bfloat16 *xh, *xl, *Wqh, *Wql, *Wkh, *Wkl, *Wvh, *Wvl;
    __nv_bfloat16 *Qh, *Ql, *Kh, *Kl, *Vth, *Vtl, *Ath, *Atl;
    float* Vf;
    cudaGetSymbolAddress((void**)&xh, g_xh);   cudaGetSymbolAddress((void**)&xl, g_xl);
    cudaGetSymbolAddress((void**)&Wqh, g_Wqh); cudaGetSymbolAddress((void**)&Wql, g_Wql);
    cudaGetSymbolAddress((void**)&Wkh, g_Wkh); cudaGetSymbolAddress((void**)&Wkl, g_Wkl);
    cudaGetSymbolAddress((void**)&Wvh, g_Wvh); cudaGetSymbolAddress((void**)&Wvl, g_Wvl);
    cudaGetSymbolAddress((void**)&Qh, g_Qh);   cudaGetSymbolAddress((void**)&Ql, g_Ql);
    cudaGetSymbolAddress((void**)&Kh, g_Kh);   cudaGetSymbolAddress((void**)&Kl, g_Kl);
    cudaGetSymbolAddress((void**)&Vth, g_Vth); cudaGetSymbolAddress((void**)&Vtl, g_Vtl);
    cudaGetSymbolAddress((void**)&Ath, g_Ath); cudaGetSymbolAddress((void**)&Atl, g_Atl);
    cudaGetSymbolAddress((void**)&Vf, g_V);

    cudaFuncSetAttribute(mma_gemm<0>, cudaFuncAttributeMaxDynamicSharedMemorySize, GEMM_SMEM);
    cudaFuncSetAttribute(mma_gemm<1>, cudaFuncAttributeMaxDynamicSharedMemorySize, GEMM_SMEM);
    cudaFuncSetAttribute(mma_gemm<2>, cudaFuncAttributeMaxDynamicSharedMemorySize, GEMM_SMEM);
    cudaFuncSetAttribute(mma_gemm<3>, cudaFuncAttributeMaxDynamicSharedMemorySize, GEMM_SMEM);

    const float inv_sqrt_d = 0.04419417382415922f;  // 1/sqrt(512)

    // 1) split inputs to bf16 hi/lo
    split_f32<<<(SEQ * DIM / 4 + 255) / 256, 256>>>(x, xh, xl, SEQ * DIM / 4);
    split_f32<<<(DIM * DIM / 4 + 255) / 256, 256>>>(Wq, Wqh, Wql, DIM * DIM / 4);
    split_f32<<<(DIM * DIM / 4 + 255) / 256, 256>>>(Wk, Wkh, Wkl, DIM * DIM / 4);
    split_f32<<<(DIM * DIM / 4 + 255) / 256, 256>>>(Wv, Wvh, Wvl, DIM * DIM / 4);

    // 2) QKV projections (tensor cores via mma.sync)
    dim3 gqkv(DIM / 128, SEQ / 128);
    mma_gemm<0><<<gqkv, 512, GEMM_SMEM>>>(xh, xl, Wqh, Wql, bq, nullptr, Qh, Ql, DIM, DIM, 1.0f);
    mma_gemm<0><<<gqkv, 512, GEMM_SMEM>>>(xh, xl, Wkh, Wkl, bk, nullptr, Kh, Kl, DIM, DIM, 1.0f);
    mma_gemm<1><<<gqkv, 512, GEMM_SMEM>>>(xh, xl, Wvh, Wvl, bv, Vf, nullptr, nullptr, DIM, DIM, 1.0f);

    // 3) V -> Vt hi/lo
    transpose_split<<<dim3(DIM / 32, SEQ / 32), 256>>>(Vf, Vth, Vtl);

    // 4) scores = (Q @ K^T) * inv_sqrt_d (lower-triangle tiles)
    dim3 gsc(SEQ / 128, SEQ / 128);
    mma_gemm<2><<<gsc, 512, GEMM_SMEM>>>(Qh, Ql, Kh, Kl, nullptr, attn, nullptr, nullptr, SEQ, DIM, inv_sqrt_d);

    // 5) causal softmax (fp32 out + bf16 hi/lo for AV)
    softmax_causal<<<SEQ, 256, SEQ * sizeof(float)>>>(attn, Ath, Atl);

    // 6) out = attn @ V  (B = Vt, K truncated per row-block)
    dim3 gav(DIM / 128, SEQ / 128);
    mma_gemm<3><<<gav, 512, GEMM_SMEM>>>(Ath, Atl, Vth, Vtl, nullptr, out, nullptr, nullptr, DIM, SEQ, 1.0f);
}